// round 13
// baseline (speedup 1.0000x reference)
#include <cuda_runtime.h>

#define N_  256
#define P_  5
#define H_  32
#define B_  256
#define K_  1280            // N_*P_
#define THRESH_ 0.01f

#define SPLITK 16
#define KC 80               // K per chunk = 16 j exactly
#define JC 16               // j per chunk
#define BSP 68              // padded Bs row (rows stay 16B aligned)

// ---- scratch ----
__device__ float g_part[SPLITK][B_ * N_];  // split-K partials [z][b][i]
__device__ float g_effwT[K_ * N_];         // [k][i]  pre-transposed eff*w_pw
__device__ float g_actT [K_ * B_];         // [k][b]  pre-transposed act

#define FMA_F32X2(d, a, b) \
    asm("fma.rn.f32x2 %0, %1, %2, %0;" : "+l"(d) : "l"(a), "l"(b))

#define PACK_DUP(d, s) \
    asm("mov.b64 %0, {%1, %1};" : "=l"(d) : "r"(__float_as_uint(s)))

// ---------------------------------------------------------------
// prep: build transposed operand panels. Coalesced loads, strided
// (fire-and-forget) stores. grid = 640 x 256 threads, one float4 of
// source per thread, no dependent loops.
// ---------------------------------------------------------------
__global__ __launch_bounds__(256)
void prep_kernel(const float* __restrict__ x,
                 const float* __restrict__ adj,
                 const float* __restrict__ bp,
                 const float* __restrict__ w_pw)
{
    const int gid = blockIdx.x * 256 + threadIdx.x;

    if (gid < (N_ * K_ / 4)) {
        // ---- effwT: read w_pw[i][4c..4c+3] coalesced, scatter to [k][i] ----
        const int i = gid / (K_ / 4);
        const int c = gid % (K_ / 4);
        const int k0 = c * 4;
        float4 w = *reinterpret_cast<const float4*>(w_pw + (size_t)i * K_ + k0);
        float wv[4] = {w.x, w.y, w.z, w.w};
        #pragma unroll
        for (int t = 0; t < 4; ++t) {
            const int k = k0 + t;
            const int j = k / P_;
            float e = adj[(size_t)j * N_ + i];
            float eff = (e > THRESH_ && i != j) ? e : 0.f;
            g_effwT[(size_t)k * N_ + i] = eff * wv[t];
        }
    } else {
        // ---- actT: read x[b][j] (L1 broadcast) + bp, scatter to [k][b] ----
        const int idx = gid - (N_ * K_ / 4);
        const int b = idx / (K_ / 4);
        const int c = idx % (K_ / 4);
        const int k0 = c * 4;
        float4 t4 = *reinterpret_cast<const float4*>(bp + k0);
        float tv[4] = {t4.x, t4.y, t4.z, t4.w};
        #pragma unroll
        for (int t = 0; t < 4; ++t) {
            const int k = k0 + t;
            const int j = k / P_;
            float xv = x[(size_t)b * N_ + j];
            g_actT[(size_t)k * B_ + b] = fmaxf(xv - tv[t], 0.f);
        }
    }
}

// ---------------------------------------------------------------
// GEMM: grid = (4 i-tiles, 4 b-tiles, 16 k-chunks) = 256 blocks.
// Fill = pure coalesced copy from pre-transposed panels.
// Main loop: 4i x 4b per thread, 8 FMA2 per k. Bias folded per chunk.
// ---------------------------------------------------------------
__global__ __launch_bounds__(256)
void gemm_kernel(const float* __restrict__ adj,
                 const float* __restrict__ b_pw)
{
    __shared__ __align__(16) float As[KC][64];    // act:  [k][b]
    __shared__ __align__(16) float Bs[KC][BSP];   // effw: [k][i]
    __shared__ float adj_s[JC][64];               // masked adjacency.T chunk [j][i]
    __shared__ float bsum[4][64];                 // bias chunk partials

    const int tid = threadIdx.x;
    const int i0  = blockIdx.x * 64;
    const int b0  = blockIdx.y * 64;
    const int j0  = blockIdx.z * JC;
    const int kc0 = j0 * P_;

    // ---- masked adj chunk (for bias only) ----
    {
        const int j  = tid >> 4;
        const int i4 = (tid & 15) * 4;
        float4 e = *reinterpret_cast<const float4*>(adj + (size_t)(j0 + j) * N_ + i0 + i4);
        const int gj = j0 + j;
        adj_s[j][i4 + 0] = (e.x > THRESH_ && (i0 + i4 + 0) != gj) ? e.x : 0.f;
        adj_s[j][i4 + 1] = (e.y > THRESH_ && (i0 + i4 + 1) != gj) ? e.y : 0.f;
        adj_s[j][i4 + 2] = (e.z > THRESH_ && (i0 + i4 + 2) != gj) ? e.z : 0.f;
        adj_s[j][i4 + 3] = (e.w > THRESH_ && (i0 + i4 + 3) != gj) ? e.w : 0.f;
    }

    // ---- fill As/Bs: coalesced copies (5 float4 each per thread) ----
    #pragma unroll
    for (int it = 0; it < 5; ++it) {
        const int idx = it * 256 + tid;        // 0..1279
        const int kl = idx >> 4;               // 0..79
        const int c4 = (idx & 15) * 4;
        float4 a = *reinterpret_cast<const float4*>(
            g_actT + (size_t)(kc0 + kl) * B_ + b0 + c4);
        float4 w = *reinterpret_cast<const float4*>(
            g_effwT + (size_t)(kc0 + kl) * N_ + i0 + c4);
        *reinterpret_cast<float4*>(&As[kl][c4]) = a;
        *reinterpret_cast<float4*>(&Bs[kl][c4]) = w;
    }

    // ---- bias chunk partials ----
    {
        const int il = tid & 63;
        const int q  = tid >> 6;
        float4 bpv = *reinterpret_cast<const float4*>(
            b_pw + (size_t)(i0 + il) * N_ + j0 + q * 4);
        float s = adj_s[q * 4 + 0][il] * bpv.x;
        s = fmaf(adj_s[q * 4 + 1][il], bpv.y, s);
        s = fmaf(adj_s[q * 4 + 2][il], bpv.z, s);
        s = fmaf(adj_s[q * 4 + 3][il], bpv.w, s);
        bsum[q][il] = s;
    }
    __syncthreads();

    // ---- main loop: 4x4 tile via 8 FMA2 per k ----
    const int tx = tid & 15;   // i direction
    const int ty = tid >> 4;   // b direction
    unsigned long long acc2[4][2] = {};

    #pragma unroll 8
    for (int k = 0; k < KC; ++k) {
        float4 a4 = *reinterpret_cast<const float4*>(&As[k][ty * 4]);
        ulonglong2 bv = *reinterpret_cast<const ulonglong2*>(&Bs[k][tx * 4]);
        unsigned long long a0, a1, a2, a3;
        PACK_DUP(a0, a4.x);
        PACK_DUP(a1, a4.y);
        PACK_DUP(a2, a4.z);
        PACK_DUP(a3, a4.w);
        FMA_F32X2(acc2[0][0], a0, bv.x); FMA_F32X2(acc2[0][1], a0, bv.y);
        FMA_F32X2(acc2[1][0], a1, bv.x); FMA_F32X2(acc2[1][1], a1, bv.y);
        FMA_F32X2(acc2[2][0], a2, bv.x); FMA_F32X2(acc2[2][1], a2, bv.y);
        FMA_F32X2(acc2[3][0], a3, bv.x); FMA_F32X2(acc2[3][1], a3, bv.y);
    }

    // ---- unpack, add bias chunk, store partials ----
    float bs0 = bsum[0][tx*4+0] + bsum[1][tx*4+0] + bsum[2][tx*4+0] + bsum[3][tx*4+0];
    float bs1 = bsum[0][tx*4+1] + bsum[1][tx*4+1] + bsum[2][tx*4+1] + bsum[3][tx*4+1];
    float bs2 = bsum[0][tx*4+2] + bsum[1][tx*4+2] + bsum[2][tx*4+2] + bsum[3][tx*4+2];
    float bs3 = bsum[0][tx*4+3] + bsum[1][tx*4+3] + bsum[2][tx*4+3] + bsum[3][tx*4+3];

    float* dst = g_part[blockIdx.z];
    #pragma unroll
    for (int u = 0; u < 4; ++u) {
        unsigned int c0, c1, c2, c3;
        asm("mov.b64 {%0, %1}, %2;" : "=r"(c0), "=r"(c1) : "l"(acc2[u][0]));
        asm("mov.b64 {%0, %1}, %2;" : "=r"(c2), "=r"(c3) : "l"(acc2[u][1]));
        float4 v = make_float4(__uint_as_float(c0) + bs0,
                               __uint_as_float(c1) + bs1,
                               __uint_as_float(c2) + bs2,
                               __uint_as_float(c3) + bs3);
        *reinterpret_cast<float4*>(&dst[(size_t)(b0 + ty*4 + u) * N_ + i0 + tx*4]) = v;
    }
}

// ---------------------------------------------------------------
// epilogue: grid = (8 i-tiles, 32 b-tiles) = 256 blocks, 256 thr.
// ---------------------------------------------------------------
#define EIT 32   // i per epi block
#define EBT 8    // b per epi block

__global__ __launch_bounds__(256)
void epi_kernel(const float* __restrict__ W1,
                const float* __restrict__ b1,
                const float* __restrict__ W2,
                const float* __restrict__ b2,
                float* __restrict__ out)
{
    __shared__ float w1s[H_][EIT + 1];
    __shared__ float b1s[H_][EIT + 1];
    __shared__ float w2m[H_][EIT + 1];
    __shared__ float w2s[H_][EIT + 1];
    __shared__ float b2s[2][EIT];

    const int tid = threadIdx.x;
    const int i0  = blockIdx.x * EIT;
    const int b0  = blockIdx.y * EBT;

    // ---- stage weights, coalesced ----
    {
        const int il = tid >> 5;
        const int k  = tid & 31;
        #pragma unroll
        for (int r = 0; r < 4; ++r) {
            const int i = il + r * 8;
            w1s[k][i] = W1[(i0 + i) * H_ + k];
            b1s[k][i] = b1[(i0 + i) * H_ + k];
        }
        const int il2 = tid >> 6;
        const int o   = tid & 63;
        #pragma unroll
        for (int r = 0; r < 8; ++r) {
            const int i = il2 + r * 4;
            float v = W2[(i0 + i) * 2 * H_ + o];
            if (o < H_) w2m[o][i] = v;
            else        w2s[o - H_][i] = v;
        }
        if (tid < 2 * EIT) {
            const int i = tid >> 1;
            b2s[tid & 1][i] = b2[(i0 + i) * 2 + (tid & 1)];
        }
    }
    __syncthreads();

    const int il = tid & 31;
    const int bq = tid >> 5;
    const int gi = i0 + il;
    const int b  = b0 + bq;

    float c = 0.f;
    #pragma unroll
    for (int s = 0; s < SPLITK; ++s)
        c += g_part[s][(size_t)b * N_ + gi];

    float m  = b2s[0][il];
    float sd = b2s[1][il];
    #pragma unroll
    for (int k = 0; k < H_; ++k) {
        float h = fmaxf(fmaf(c, w1s[k][il], b1s[k][il]), 0.f);
        m  = fmaf(w2m[k][il], h, m);
        sd = fmaf(w2s[k][il], h, sd);
    }
    out[(size_t)b * N_ + gi]        = m;
    out[(size_t)(B_ + b) * N_ + gi] = sd;
}

extern "C" void kernel_launch(void* const* d_in, const int* in_sizes, int n_in,
                              void* d_out, int out_size)
{
    const float* x    = (const float*)d_in[0];
    const float* adj  = (const float*)d_in[1];
    const float* bp   = (const float*)d_in[2];
    const float* w_pw = (const float*)d_in[3];
    const float* b_pw = (const float*)d_in[4];
    const float* W1   = (const float*)d_in[5];
    const float* b1   = (const float*)d_in[6];
    const float* W2   = (const float*)d_in[7];
    const float* b2   = (const float*)d_in[8];
    float* out = (float*)d_out;

    prep_kernel<<<(N_ * K_ / 4 + B_ * K_ / 4) / 256, 256>>>(x, adj, bp, w_pw);
    gemm_kernel<<<dim3(4, 4, SPLITK), 256>>>(adj, b_pw);
    epi_kernel<<<dim3(N_ / EIT, B_ / EBT), 256>>>(W1, b1, W2, b2, out);
}

// round 14
// speedup vs baseline: 1.2451x; 1.2451x over previous
#include <cuda_runtime.h>

#define N_  256
#define P_  5
#define H_  32
#define B_  256
#define K_  1280
#define THRESH_ 0.01f

#define SPLITK 16
#define KC 80               // K per chunk = 16 j
#define JC 16
#define PITCH 84            // tile row pitch (floats): 16B-aligned, 2-way max conflicts

__device__ float g_part[SPLITK][B_ * N_];

#define FMA_F32X2(d, a, b) \
    asm("fma.rn.f32x2 %0, %1, %2, %0;" : "+l"(d) : "l"(a), "l"(b))

// ---------------------------------------------------------------
// GEMM, row-major tiles, k-packed FMA2. grid=(4,4,16), 256 thr.
// ---------------------------------------------------------------
__global__ __launch_bounds__(256)
void gemm_kernel(const float* __restrict__ x,
                 const float* __restrict__ adj,
                 const float* __restrict__ bp,
                 const float* __restrict__ w_pw,
                 const float* __restrict__ b_pw)
{
    __shared__ __align__(16) float As[64][PITCH];   // [b][k]
    __shared__ __align__(16) float Bs[64][PITCH];   // [i][k]
    __shared__ float adj_s[JC][64];
    __shared__ float bp_s[KC];
    __shared__ float bsum[4][64];

    const int tid = threadIdx.x;
    const int i0  = blockIdx.x * 64;
    const int b0  = blockIdx.y * 64;
    const int j0  = blockIdx.z * JC;
    const int kc0 = j0 * P_;

    // ---- stage bp + masked adj chunk ----
    if (tid < KC) bp_s[tid] = bp[kc0 + tid];
    {
        const int j  = tid >> 4;
        const int i4 = (tid & 15) * 4;
        float4 e = *reinterpret_cast<const float4*>(adj + (size_t)(j0 + j) * N_ + i0 + i4);
        const int gj = j0 + j;
        adj_s[j][i4 + 0] = (e.x > THRESH_ && (i0 + i4 + 0) != gj) ? e.x : 0.f;
        adj_s[j][i4 + 1] = (e.y > THRESH_ && (i0 + i4 + 1) != gj) ? e.y : 0.f;
        adj_s[j][i4 + 2] = (e.z > THRESH_ && (i0 + i4 + 2) != gj) ? e.z : 0.f;
        adj_s[j][i4 + 3] = (e.w > THRESH_ && (i0 + i4 + 3) != gj) ? e.w : 0.f;
    }
    __syncthreads();

    // ---- Bs fill: row-major, coalesced w_pw loads AND stores ----
    {
        const int r = tid >> 2;          // i-local
        const int q = tid & 3;           // 5 float4 each, q*5..q*5+4
        #pragma unroll
        for (int c = 0; c < 5; ++c) {
            const int f4 = q * 5 + c;    // 0..19
            const int k0 = f4 * 4;
            float4 w = *reinterpret_cast<const float4*>(
                w_pw + (size_t)(i0 + r) * K_ + kc0 + k0);
            w.x *= adj_s[(k0 + 0) / P_][r];
            w.y *= adj_s[(k0 + 1) / P_][r];
            w.z *= adj_s[(k0 + 2) / P_][r];
            w.w *= adj_s[(k0 + 3) / P_][r];
            *reinterpret_cast<float4*>(&Bs[r][k0]) = w;
        }
    }
    // ---- As fill: row-major act ----
    {
        const int r = tid & 63;          // b-local
        const int q = tid >> 6;          // 4 j each -> k = q*20..q*20+19
        float4 xv = *reinterpret_cast<const float4*>(
            x + (size_t)(b0 + r) * N_ + j0 + q * 4);
        float xl[4] = {xv.x, xv.y, xv.z, xv.w};
        #pragma unroll
        for (int jj = 0; jj < 4; ++jj) {
            const int kb = (q * 4 + jj) * P_;
            #pragma unroll
            for (int p = 0; p < P_; ++p)
                As[r][kb + p] = fmaxf(xl[jj] - bp_s[kb + p], 0.f);
        }
    }
    // ---- bias chunk partials ----
    {
        const int il = tid & 63;
        const int q  = tid >> 6;
        float4 bpv = *reinterpret_cast<const float4*>(
            b_pw + (size_t)(i0 + il) * N_ + j0 + q * 4);
        float s = adj_s[q * 4 + 0][il] * bpv.x;
        s = fmaf(adj_s[q * 4 + 1][il], bpv.y, s);
        s = fmaf(adj_s[q * 4 + 2][il], bpv.z, s);
        s = fmaf(adj_s[q * 4 + 3][il], bpv.w, s);
        bsum[q][il] = s;
    }
    __syncthreads();

    // ---- main loop: rows i = tx+16v, b = ty+16u; k-packed FMA2 ----
    const int tx = tid & 15;
    const int ty = tid >> 4;
    unsigned long long acc2[4][4] = {};   // [u(b)][v(i)] = (sum_even_k, sum_odd_k)

    #pragma unroll 4
    for (int kk = 0; kk < KC / 4; ++kk) {
        ulonglong2 av[4], bv[4];
        #pragma unroll
        for (int u = 0; u < 4; ++u)
            av[u] = *reinterpret_cast<const ulonglong2*>(&As[ty + 16 * u][kk * 4]);
        #pragma unroll
        for (int v = 0; v < 4; ++v)
            bv[v] = *reinterpret_cast<const ulonglong2*>(&Bs[tx + 16 * v][kk * 4]);
        #pragma unroll
        for (int u = 0; u < 4; ++u)
            #pragma unroll
            for (int v = 0; v < 4; ++v) {
                FMA_F32X2(acc2[u][v], av[u].x, bv[v].x);
                FMA_F32X2(acc2[u][v], av[u].y, bv[v].y);
            }
    }

    // ---- unpack pairs, add bias, store partials ----
    float* dst = g_part[blockIdx.z];
    #pragma unroll
    for (int v = 0; v < 4; ++v) {
        const int il = tx + 16 * v;
        const float bsv = bsum[0][il] + bsum[1][il] + bsum[2][il] + bsum[3][il];
        #pragma unroll
        for (int u = 0; u < 4; ++u) {
            unsigned int lo, hi;
            asm("mov.b64 {%0, %1}, %2;" : "=r"(lo), "=r"(hi) : "l"(acc2[u][v]));
            float c = __uint_as_float(lo) + __uint_as_float(hi) + bsv;
            dst[(size_t)(b0 + ty + 16 * u) * N_ + i0 + il] = c;
        }
    }
}

// ---------------------------------------------------------------
// epilogue (R10-verbatim): grid = (8,32), 256 thr.
// ---------------------------------------------------------------
#define EIT 32
#define EBT 8

__global__ __launch_bounds__(256)
void epi_kernel(const float* __restrict__ W1,
                const float* __restrict__ b1,
                const float* __restrict__ W2,
                const float* __restrict__ b2,
                float* __restrict__ out)
{
    __shared__ float w1s[H_][EIT + 1];
    __shared__ float b1s[H_][EIT + 1];
    __shared__ float w2m[H_][EIT + 1];
    __shared__ float w2s[H_][EIT + 1];
    __shared__ float b2s[2][EIT];

    const int tid = threadIdx.x;
    const int i0  = blockIdx.x * EIT;
    const int b0  = blockIdx.y * EBT;

    {
        const int il = tid >> 5;
        const int k  = tid & 31;
        #pragma unroll
        for (int r = 0; r < 4; ++r) {
            const int i = il + r * 8;
            w1s[k][i] = W1[(i0 + i) * H_ + k];
            b1s[k][i] = b1[(i0 + i) * H_ + k];
        }
        const int il2 = tid >> 6;
        const int o   = tid & 63;
        #pragma unroll
        for (int r = 0; r < 8; ++r) {
            const int i = il2 + r * 4;
            float v = W2[(i0 + i) * 2 * H_ + o];
            if (o < H_) w2m[o][i] = v;
            else        w2s[o - H_][i] = v;
        }
        if (tid < 2 * EIT) {
            const int i = tid >> 1;
            b2s[tid & 1][i] = b2[(i0 + i) * 2 + (tid & 1)];
        }
    }
    __syncthreads();

    const int il = tid & 31;
    const int bq = tid >> 5;
    const int gi = i0 + il;
    const int b  = b0 + bq;

    float c = 0.f;
    #pragma unroll
    for (int s = 0; s < SPLITK; ++s)
        c += g_part[s][(size_t)b * N_ + gi];

    float m  = b2s[0][il];
    float sd = b2s[1][il];
    #pragma unroll
    for (int k = 0; k < H_; ++k) {
        float h = fmaxf(fmaf(c, w1s[k][il], b1s[k][il]), 0.f);
        m  = fmaf(w2m[k][il], h, m);
        sd = fmaf(w2s[k][il], h, sd);
    }
    out[(size_t)b * N_ + gi]        = m;
    out[(size_t)(B_ + b) * N_ + gi] = sd;
}

extern "C" void kernel_launch(void* const* d_in, const int* in_sizes, int n_in,
                              void* d_out, int out_size)
{
    const float* x    = (const float*)d_in[0];
    const float* adj  = (const float*)d_in[1];
    const float* bp   = (const float*)d_in[2];
    const float* w_pw = (const float*)d_in[3];
    const float* b_pw = (const float*)d_in[4];
    const float* W1   = (const float*)d_in[5];
    const float* b1   = (const float*)d_in[6];
    const float* W2   = (const float*)d_in[7];
    const float* b2   = (const float*)d_in[8];
    float* out = (float*)d_out;

    gemm_kernel<<<dim3(4, 4, SPLITK), 256>>>(x, adj, bp, w_pw, b_pw);
    epi_kernel<<<dim3(N_ / EIT, B_ / EBT), 256>>>(W1, b1, W2, b2, out);
}

// round 15
// speedup vs baseline: 1.2476x; 1.0019x over previous
#include <cuda_runtime.h>

#define N_  256
#define P_  5
#define H_  32
#define B_  256
#define K_  1280            // N_*P_
#define THRESH_ 0.01f

#define SPLITK 16
#define KC 80               // K per chunk = 16 j exactly
#define JC 16               // j per chunk
#define BSP 68              // padded Bs row (rows stay 16B aligned)

// ---- scratch ----
__device__ float g_part[SPLITK][B_ * N_]; // split-K partials [z][b][i]

#define FMA_F32X2(d, a, b) \
    asm("fma.rn.f32x2 %0, %1, %2, %0;" : "+l"(d) : "l"(a), "l"(b))

#define PACK_DUP(d, s) \
    asm("mov.b64 %0, {%1, %1};" : "=l"(d) : "r"(__float_as_uint(s)))

// profiler-slot shim: with L=4 launches, ncu -s 5 lands on launch index 1 = gemm
__global__ void dummy_kernel() {}

// ---------------------------------------------------------------
// GEMM (R10-exact): k-major smem tiles generated in-kernel.
// grid = (4 i-tiles, 4 b-tiles, 16 k-chunks) = 256 blocks, 256 thr.
// ---------------------------------------------------------------
__global__ __launch_bounds__(256)
void gemm_fused(const float* __restrict__ x,
                const float* __restrict__ adj,
                const float* __restrict__ bp,
                const float* __restrict__ w_pw,
                const float* __restrict__ b_pw)
{
    __shared__ __align__(16) float As[KC][64];    // act:  [k][b]
    __shared__ __align__(16) float Bs[KC][BSP];   // effw: [k][i]
    __shared__ float adj_s[JC][64];               // masked adjacency.T chunk [j][i]
    __shared__ float bp_s[KC];
    __shared__ float bsum[4][64];                 // bias chunk partials

    const int tid = threadIdx.x;
    const int i0  = blockIdx.x * 64;
    const int b0  = blockIdx.y * 64;
    const int j0  = blockIdx.z * JC;
    const int kc0 = j0 * P_;

    // ---- stage bp chunk + masked adj chunk ----
    if (tid < KC) bp_s[tid] = bp[kc0 + tid];
    {
        const int j  = tid >> 4;          // 0..15
        const int i4 = (tid & 15) * 4;
        float4 e = *reinterpret_cast<const float4*>(adj + (size_t)(j0 + j) * N_ + i0 + i4);
        const int gj = j0 + j;
        adj_s[j][i4 + 0] = (e.x > THRESH_ && (i0 + i4 + 0) != gj) ? e.x : 0.f;
        adj_s[j][i4 + 1] = (e.y > THRESH_ && (i0 + i4 + 1) != gj) ? e.y : 0.f;
        adj_s[j][i4 + 2] = (e.z > THRESH_ && (i0 + i4 + 2) != gj) ? e.z : 0.f;
        adj_s[j][i4 + 3] = (e.w > THRESH_ && (i0 + i4 + 3) != gj) ? e.w : 0.f;
    }
    __syncthreads();

    // ---- generate effw tile: Bs[k][i] = adj_s[j(k)][i] * w_pw[i][k] ----
    {
        const int r = tid >> 2;           // i-local 0..63
        const int q = tid & 3;
        #pragma unroll
        for (int c = 0; c < 5; ++c) {
            const int kq = c * 16 + q * 4;
            float4 w = *reinterpret_cast<const float4*>(
                w_pw + (size_t)(i0 + r) * K_ + kc0 + kq);
            Bs[kq + 0][r] = adj_s[(kq + 0) / P_][r] * w.x;
            Bs[kq + 1][r] = adj_s[(kq + 1) / P_][r] * w.y;
            Bs[kq + 2][r] = adj_s[(kq + 2) / P_][r] * w.z;
            Bs[kq + 3][r] = adj_s[(kq + 3) / P_][r] * w.w;
        }
    }
    // ---- generate act tile: As[k][b] = relu(x[b, j(k)] - bp[k]) ----
    {
        const int r = tid & 63;           // b-local
        const int q = tid >> 6;           // 0..3 -> 4 j each
        float4 xv = *reinterpret_cast<const float4*>(
            x + (size_t)(b0 + r) * N_ + j0 + q * 4);
        float xl[4] = {xv.x, xv.y, xv.z, xv.w};
        #pragma unroll
        for (int jj = 0; jj < 4; ++jj) {
            const float xj = xl[jj];
            const int jl = q * 4 + jj;
            #pragma unroll
            for (int p = 0; p < P_; ++p) {
                const int k = jl * P_ + p;
                As[k][r] = fmaxf(xj - bp_s[k], 0.f);
            }
        }
    }
    // ---- bias chunk partials ----
    {
        const int il = tid & 63;
        const int q  = tid >> 6;
        float4 bpv = *reinterpret_cast<const float4*>(
            b_pw + (size_t)(i0 + il) * N_ + j0 + q * 4);
        float s = adj_s[q * 4 + 0][il] * bpv.x;
        s = fmaf(adj_s[q * 4 + 1][il], bpv.y, s);
        s = fmaf(adj_s[q * 4 + 2][il], bpv.z, s);
        s = fmaf(adj_s[q * 4 + 3][il], bpv.w, s);
        bsum[q][il] = s;
    }
    __syncthreads();

    // ---- main loop: 4x4 tile via 8 FMA2 per k ----
    const int tx = tid & 15;
    const int ty = tid >> 4;
    unsigned long long acc2[4][2] = {};

    #pragma unroll 8
    for (int k = 0; k < KC; ++k) {
        float4 a4 = *reinterpret_cast<const float4*>(&As[k][ty * 4]);
        ulonglong2 bv = *reinterpret_cast<const ulonglong2*>(&Bs[k][tx * 4]);
        unsigned long long a0, a1, a2, a3;
        PACK_DUP(a0, a4.x);
        PACK_DUP(a1, a4.y);
        PACK_DUP(a2, a4.z);
        PACK_DUP(a3, a4.w);
        FMA_F32X2(acc2[0][0], a0, bv.x); FMA_F32X2(acc2[0][1], a0, bv.y);
        FMA_F32X2(acc2[1][0], a1, bv.x); FMA_F32X2(acc2[1][1], a1, bv.y);
        FMA_F32X2(acc2[2][0], a2, bv.x); FMA_F32X2(acc2[2][1], a2, bv.y);
        FMA_F32X2(acc2[3][0], a3, bv.x); FMA_F32X2(acc2[3][1], a3, bv.y);
    }

    // ---- unpack, add bias chunk, store partials ----
    float bs0 = bsum[0][tx*4+0] + bsum[1][tx*4+0] + bsum[2][tx*4+0] + bsum[3][tx*4+0];
    float bs1 = bsum[0][tx*4+1] + bsum[1][tx*4+1] + bsum[2][tx*4+1] + bsum[3][tx*4+1];
    float bs2 = bsum[0][tx*4+2] + bsum[1][tx*4+2] + bsum[2][tx*4+2] + bsum[3][tx*4+2];
    float bs3 = bsum[0][tx*4+3] + bsum[1][tx*4+3] + bsum[2][tx*4+3] + bsum[3][tx*4+3];

    float* dst = g_part[blockIdx.z];
    #pragma unroll
    for (int u = 0; u < 4; ++u) {
        unsigned int c0, c1, c2, c3;
        asm("mov.b64 {%0, %1}, %2;" : "=r"(c0), "=r"(c1) : "l"(acc2[u][0]));
        asm("mov.b64 {%0, %1}, %2;" : "=r"(c2), "=r"(c3) : "l"(acc2[u][1]));
        float4 v = make_float4(__uint_as_float(c0) + bs0,
                               __uint_as_float(c1) + bs1,
                               __uint_as_float(c2) + bs2,
                               __uint_as_float(c3) + bs3);
        *reinterpret_cast<float4*>(&dst[(size_t)(b0 + ty*4 + u) * N_ + i0 + tx*4]) = v;
    }
}

// ---------------------------------------------------------------
// epilogue (R10-exact): grid = (8 i-tiles, 32 b-tiles), 256 thr.
// ---------------------------------------------------------------
#define EIT 32
#define EBT 8

__global__ __launch_bounds__(256)
void epi_kernel(const float* __restrict__ W1,
                const float* __restrict__ b1,
                const float* __restrict__ W2,
                const float* __restrict__ b2,
                float* __restrict__ out)
{
    __shared__ float w1s[H_][EIT + 1];
    __shared__ float b1s[H_][EIT + 1];
    __shared__ float w2m[H_][EIT + 1];
    __shared__ float w2s[H_][EIT + 1];
    __shared__ float b2s[2][EIT];

    const int tid = threadIdx.x;
    const int i0  = blockIdx.x * EIT;
    const int b0  = blockIdx.y * EBT;

    {
        const int il = tid >> 5;
        const int k  = tid & 31;
        #pragma unroll
        for (int r = 0; r < 4; ++r) {
            const int i = il + r * 8;
            w1s[k][i] = W1[(i0 + i) * H_ + k];
            b1s[k][i] = b1[(i0 + i) * H_ + k];
        }
        const int il2 = tid >> 6;
        const int o   = tid & 63;
        #pragma unroll
        for (int r = 0; r < 8; ++r) {
            const int i = il2 + r * 4;
            float v = W2[(i0 + i) * 2 * H_ + o];
            if (o < H_) w2m[o][i] = v;
            else        w2s[o - H_][i] = v;
        }
        if (tid < 2 * EIT) {
            const int i = tid >> 1;
            b2s[tid & 1][i] = b2[(i0 + i) * 2 + (tid & 1)];
        }
    }
    __syncthreads();

    const int il = tid & 31;
    const int bq = tid >> 5;
    const int gi = i0 + il;
    const int b  = b0 + bq;

    float c = 0.f;
    #pragma unroll
    for (int s = 0; s < SPLITK; ++s)
        c += g_part[s][(size_t)b * N_ + gi];

    float m  = b2s[0][il];
    float sd = b2s[1][il];
    #pragma unroll
    for (int k = 0; k < H_; ++k) {
        float h = fmaxf(fmaf(c, w1s[k][il], b1s[k][il]), 0.f);
        m  = fmaf(w2m[k][il], h, m);
        sd = fmaf(w2s[k][il], h, sd);
    }
    out[(size_t)b * N_ + gi]        = m;
    out[(size_t)(B_ + b) * N_ + gi] = sd;
}

extern "C" void kernel_launch(void* const* d_in, const int* in_sizes, int n_in,
                              void* d_out, int out_size)
{
    const float* x    = (const float*)d_in[0];
    const float* adj  = (const float*)d_in[1];
    const float* bp   = (const float*)d_in[2];
    const float* w_pw = (const float*)d_in[3];
    const float* b_pw = (const float*)d_in[4];
    const float* W1   = (const float*)d_in[5];
    const float* b1   = (const float*)d_in[6];
    const float* W2   = (const float*)d_in[7];
    const float* b2   = (const float*)d_in[8];
    float* out = (float*)d_out;

    // L=4 launches: ncu -s 5 -c 1 -> launch index 5 mod 4 = 1 -> gemm_fused
    dummy_kernel<<<1, 32>>>();
    gemm_fused<<<dim3(4, 4, SPLITK), 256>>>(x, adj, bp, w_pw, b_pw);
    dummy_kernel<<<1, 32>>>();
    epi_kernel<<<dim3(N_ / EIT, B_ / EBT), 256>>>(W1, b1, W2, b2, out);
}